// round 1
// baseline (speedup 1.0000x reference)
#include <cuda_runtime.h>
#include <math.h>

#define NUM_C   10
#define NUM_R   1152
#define IN_CH   8
#define OUT_CH  16
#define BATCH   256
#define KDIM    (NUM_R * IN_CH)      /* 9216 */
#define NCOL    (NUM_C * OUT_CH)     /* 160  */

#define KSPLIT   58
#define KT       32
#define CP       2                   /* capsules per block */
#define NTHREADS 256

/* split-K partial sums: [KSPLIT][BATCH][NCOL] — static device scratch (no allocs) */
__device__ float g_Upart[KSPLIT * BATCH * NCOL];

__device__ __forceinline__ unsigned long long bcast_f32x2(float a) {
    unsigned long long r;
    asm("mov.b64 %0, {%1, %1};" : "=l"(r) : "f"(a));
    return r;
}
__device__ __forceinline__ void fma_f32x2(unsigned long long& d,
                                          unsigned long long a,
                                          unsigned long long b) {
    asm("fma.rn.f32x2 %0, %1, %2, %0;" : "+l"(d) : "l"(a), "l"(b));
}
__device__ __forceinline__ float2 unpack_f32x2(unsigned long long v) {
    float2 r;
    asm("mov.b64 {%0, %1}, %2;" : "=f"(r.x), "=f"(r.y) : "l"(v));
    return r;
}

/* GEMM: U[b, c*16+o] = sum_k x[b,k] * W[c,k,o]  (k = r*8+i)
 * grid = (KSPLIT, NUM_C/CP), block = 256 threads.
 * Thread: oh = tid&1 (8 o's), bq = tid>>1 (2 b's). Acc = 2b x 2c x 8o = 16 f32x2. */
__global__ __launch_bounds__(NTHREADS, 2)
void gemm_kernel(const float* __restrict__ x, const float* __restrict__ w) {
    __shared__ __align__(16) float sx[BATCH * (KT + 1)];
    __shared__ __align__(16) float sw[CP][KT * OUT_CH];

    const int kc  = blockIdx.x;
    const int c0  = blockIdx.y * CP;
    const int tid = threadIdx.x;
    const int oh  = tid & 1;
    const int bq  = tid >> 1;

    /* K range for this split, float4-aligned boundaries */
    const int start4 = (kc * (KDIM / 4)) / KSPLIT;
    const int end4   = ((kc + 1) * (KDIM / 4)) / KSPLIT;
    const int kstart = start4 * 4;
    const int kend   = end4 * 4;

    unsigned long long acc[CP][2][4];
    #pragma unroll
    for (int cc = 0; cc < CP; cc++)
        #pragma unroll
        for (int bi = 0; bi < 2; bi++)
            #pragma unroll
            for (int p = 0; p < 4; p++) acc[cc][bi][p] = 0ull;

    const float4* __restrict__ x4 = (const float4*)x;
    const float4* __restrict__ w4 = (const float4*)w;

    for (int k0 = kstart; k0 < kend; k0 += KT) {
        /* stage x tile [256 b][KT k] into smem, row stride KT+1 (conflict-free) */
        #pragma unroll
        for (int j = 0; j < 8; j++) {
            int fid = j * NTHREADS + tid;
            int row = fid >> 3;          /* KT/4 = 8 float4 per row */
            int col = fid & 7;
            float4 v = make_float4(0.f, 0.f, 0.f, 0.f);
            if (k0 + col * 4 < kend)
                v = x4[row * (KDIM / 4) + (k0 >> 2) + col];
            float* sp = &sx[row * (KT + 1) + col * 4];
            sp[0] = v.x; sp[1] = v.y; sp[2] = v.z; sp[3] = v.w;
        }
        /* stage W tiles: per c, KT*16 contiguous floats = 128 float4 */
        {
            int cc = tid >> 7;           /* 0..1 */
            int f  = tid & 127;
            int kk = f >> 2;
            float4 v = make_float4(0.f, 0.f, 0.f, 0.f);
            if (k0 + kk < kend)
                v = w4[(size_t)((c0 + cc) * KDIM + k0) * 4 + f];
            ((float4*)sw[cc])[f] = v;
        }
        __syncthreads();

        const float* sxa = &sx[(bq * 2 + 0) * (KT + 1)];
        const float* sxb = &sx[(bq * 2 + 1) * (KT + 1)];
        #pragma unroll 8
        for (int kk = 0; kk < KT; kk++) {
            unsigned long long xa = bcast_f32x2(sxa[kk]);
            unsigned long long xb = bcast_f32x2(sxb[kk]);
            #pragma unroll
            for (int cc = 0; cc < CP; cc++) {
                const ulonglong2* swp =
                    (const ulonglong2*)&sw[cc][kk * OUT_CH + oh * 8];
                ulonglong2 wA = swp[0];  /* o pairs (0,1),(2,3) of this half */
                ulonglong2 wB = swp[1];  /* o pairs (4,5),(6,7) */
                fma_f32x2(acc[cc][0][0], xa, wA.x);
                fma_f32x2(acc[cc][0][1], xa, wA.y);
                fma_f32x2(acc[cc][0][2], xa, wB.x);
                fma_f32x2(acc[cc][0][3], xa, wB.y);
                fma_f32x2(acc[cc][1][0], xb, wA.x);
                fma_f32x2(acc[cc][1][1], xb, wA.y);
                fma_f32x2(acc[cc][1][2], xb, wB.x);
                fma_f32x2(acc[cc][1][3], xb, wB.y);
            }
        }
        __syncthreads();
    }

    /* write split-K partials (each element written exactly once -> deterministic) */
    #pragma unroll
    for (int cc = 0; cc < CP; cc++) {
        #pragma unroll
        for (int bi = 0; bi < 2; bi++) {
            int b = bq * 2 + bi;
            float2 f0 = unpack_f32x2(acc[cc][bi][0]);
            float2 f1 = unpack_f32x2(acc[cc][bi][1]);
            float2 f2 = unpack_f32x2(acc[cc][bi][2]);
            float2 f3 = unpack_f32x2(acc[cc][bi][3]);
            size_t base = ((size_t)kc * BATCH + b) * NCOL
                        + (size_t)(c0 + cc) * OUT_CH + oh * 8;
            float4* dst = (float4*)&g_Upart[base];
            dst[0] = make_float4(f0.x, f0.y, f1.x, f1.y);
            dst[1] = make_float4(f2.x, f2.y, f3.x, f3.y);
        }
    }
}

/* Reduce split-K partials + 3-iteration routing (collapsed: probs are r-independent).
 * grid = BATCH blocks, 160 threads: tid = c*16 + o. */
__global__ void routing_kernel(float* __restrict__ out) {
    const int b   = blockIdx.x;
    const int tid = threadIdx.x;  /* 0..159 */
    const int c   = tid >> 4;
    const int o   = tid & 15;

    float u = 0.f;
    #pragma unroll 8
    for (int kc = 0; kc < KSPLIT; kc++)
        u += g_Upart[((size_t)kc * BATCH + b) * NCOL + tid];

    __shared__ float L[NUM_C];
    if (tid < NUM_C) L[tid] = 0.f;
    __syncthreads();

    float v = 0.f;
    for (int it = 0; it < 3; it++) {
        /* softmax over capsules (redundant per thread, 10 elems) */
        float mx = L[0];
        #pragma unroll
        for (int j = 1; j < NUM_C; j++) mx = fmaxf(mx, L[j]);
        float den = 0.f;
        #pragma unroll
        for (int j = 0; j < NUM_C; j++) den += expf(L[j] - mx);
        float p = expf(L[c] - mx) / den;

        /* outputs = squash(p*u): elementwise t*|t|/(1+t^2) (axis-2 has size 1) */
        float t = p * u;
        v = t * fabsf(t) / (1.f + t * t);

        /* S[c] = sum_o v  (16-lane groups aligned within warps) */
        float S = v;
        S += __shfl_xor_sync(0xffffffffu, S, 8);
        S += __shfl_xor_sync(0xffffffffu, S, 4);
        S += __shfl_xor_sync(0xffffffffu, S, 2);
        S += __shfl_xor_sync(0xffffffffu, S, 1);

        __syncthreads();
        if (o == 0) L[c] += p * S;   /* change = p * S, broadcast over r and o */
        __syncthreads();
    }

    out[(size_t)b * NCOL + tid] = v;
}

extern "C" void kernel_launch(void* const* d_in, const int* in_sizes, int n_in,
                              void* d_out, int out_size) {
    const float* x = (const float*)d_in[0];
    const float* w = (const float*)d_in[1];
    /* defensive: identify by element count (x: 2359296, W: 1474560) */
    if (n_in >= 2 && in_sizes[0] == NUM_C * NUM_R * IN_CH * OUT_CH) {
        w = (const float*)d_in[0];
        x = (const float*)d_in[1];
    }
    dim3 grid(KSPLIT, NUM_C / CP);
    gemm_kernel<<<grid, NTHREADS>>>(x, w);
    routing_kernel<<<BATCH, NCOL>>>((float*)d_out);
    (void)out_size;
}